// round 7
// baseline (speedup 1.0000x reference)
#include <cuda_runtime.h>
#include <cuda_bf16.h>
#include <cstdint>
#include <math.h>

#define N_NODES 50000
#define N_EDGES 800000
#define F 64          // F_IN == F_HID
#define KTOT 192      // x | tx1 | y
#define NOUT 128      // z (64) | h (64)
#define SCAN_TILE 1024
#define MAX_BLOCKS ((N_NODES + SCAN_TILE - 1) / SCAN_TILE + 1)

// ---------------- device scratch (allocation-free) ----------------
// Self-cleaning invariant: every kernel_launch call leaves g_deg/g_count/g_pack
// zeroed for the next call (first call sees .bss zeros from module load).
__device__ float g_deg[N_NODES];
__device__ float g_dis[N_NODES];
__device__ int   g_count[N_NODES];
__device__ int   g_rowptr[N_NODES + 1];
__device__ int   g_cursor[N_NODES];
__device__ unsigned long long g_pack[MAX_BLOCKS];   // lookback state (flag<<32 | value)
__device__ __align__(16) int2 g_edge[N_EDGES];      // (src, norm-bits)
__device__ __align__(16) float g_tx1[N_NODES * F];
__device__ __align__(16) __nv_bfloat16 g_Ahi[N_NODES * KTOT];
__device__ __align__(16) __nv_bfloat16 g_Alo[N_NODES * KTOT];
__device__ __align__(16) __nv_bfloat16 g_Bhi[NOUT * KTOT];   // [n][k], k-contiguous
__device__ __align__(16) __nv_bfloat16 g_Blo[NOUT * KTOT];
__device__ float g_bz[F];
__device__ float g_bh[F];

// ---------------- PTX helpers ----------------
__device__ __forceinline__ uint32_t smem_u32(const void* p) {
    uint32_t a;
    asm("{ .reg .u64 t; cvta.to.shared.u64 t, %1; cvt.u32.u64 %0, t; }" : "=r"(a) : "l"(p));
    return a;
}
__device__ __forceinline__ void ldsm4(uint32_t (&d)[4], uint32_t addr) {
    asm volatile("ldmatrix.sync.aligned.m8n8.x4.shared.b16 {%0,%1,%2,%3}, [%4];\n"
                 : "=r"(d[0]), "=r"(d[1]), "=r"(d[2]), "=r"(d[3]) : "r"(addr));
}
__device__ __forceinline__ void mma_bf16(float (&c)[4], const uint32_t (&a)[4],
                                         uint32_t b0, uint32_t b1) {
    asm volatile(
        "mma.sync.aligned.m16n8k16.row.col.f32.bf16.bf16.f32 "
        "{%0,%1,%2,%3}, {%4,%5,%6,%7}, {%8,%9}, {%0,%1,%2,%3};\n"
        : "+f"(c[0]), "+f"(c[1]), "+f"(c[2]), "+f"(c[3])
        : "r"(a[0]), "r"(a[1]), "r"(a[2]), "r"(a[3]), "r"(b0), "r"(b1));
}

// ---------------- kernels ----------------

__global__ void edge_pass1_kernel(const int* __restrict__ ei,
                                  const float* __restrict__ ew, int E) {
    int e = blockIdx.x * blockDim.x + threadIdx.x;
    if (e >= E) return;
    atomicAdd(&g_deg[ei[e]], ew[e]);
    atomicAdd(&g_count[ei[E + e]], 1);
}

// Single-kernel decoupled-lookback exclusive scan of g_count.
// Also: fills g_cursor, computes g_dis, and zeroes g_count/g_deg for next replay.
__global__ void scan_kernel(int n, int nb) {
    __shared__ int warp_sums[32];
    __shared__ int s_excl;
    int tid = threadIdx.x, lane = tid & 31, wid = tid >> 5;
    int b = blockIdx.x;
    int i = b * SCAN_TILE + tid;
    int v = (i < n) ? g_count[i] : 0;
    int incl = v;
    #pragma unroll
    for (int o = 1; o < 32; o <<= 1) {
        int t = __shfl_up_sync(0xffffffffu, incl, o);
        if (lane >= o) incl += t;
    }
    if (lane == 31) warp_sums[wid] = incl;
    __syncthreads();
    if (wid == 0) {
        int s = warp_sums[lane];
        int sincl = s;
        #pragma unroll
        for (int o = 1; o < 32; o <<= 1) {
            int t = __shfl_up_sync(0xffffffffu, sincl, o);
            if (lane >= o) sincl += t;
        }
        warp_sums[lane] = sincl - s;          // exclusive over warps
        int total = __shfl_sync(0xffffffffu, sincl, 31);
        if (b == 0) {
            if (lane == 0) {
                atomicExch(&g_pack[0], (2ULL << 32) | (unsigned)total);
                s_excl = 0;
            }
        } else {
            if (lane == 0)
                atomicExch(&g_pack[b], (1ULL << 32) | (unsigned)total);
            // warp-wide lookback: 32 predecessors per round
            int excl = 0;
            int base = b - 1;
            bool done = false;
            while (!done) {
                int idx = base - lane;
                unsigned long long pk = (idx >= 0)
                    ? atomicAdd(&g_pack[idx], 0ULL) : (2ULL << 32);
                unsigned flag = (unsigned)(pk >> 32);
                int val = (int)(unsigned)pk;
                unsigned m2 = __ballot_sync(0xffffffffu, flag == 2u);
                unsigned m0 = __ballot_sync(0xffffffffu, flag == 0u);
                int f2 = __ffs(m2) - 1;   // lowest lane (= nearest pred) with inclusive
                unsigned need = (f2 >= 0) ? ((1u << f2) - 1u) : 0xffffffffu;
                if (m0 & need) continue;  // someone needed not published yet
                int contrib;
                if (f2 >= 0) { contrib = (lane <= f2) ? val : 0; done = true; }
                else         { contrib = val; base -= 32; }
                #pragma unroll
                for (int o = 16; o > 0; o >>= 1)
                    contrib += __shfl_xor_sync(0xffffffffu, contrib, o);
                excl += contrib;
            }
            if (lane == 0) {
                atomicExch(&g_pack[b], (2ULL << 32) | (unsigned)(excl + total));
                s_excl = excl;
            }
        }
    }
    __syncthreads();
    int val = s_excl + warp_sums[wid] + incl - v;
    if (i < n) {
        g_rowptr[i] = val;
        g_cursor[i] = val;
        g_count[i] = 0;                       // reset for next replay
        float d = g_deg[i];
        g_dis[i] = (d > 0.0f) ? rsqrtf(d) : 0.0f;
        g_deg[i] = 0.0f;                      // reset for next replay
    }
    if (i == n - 1) g_rowptr[n] = val + v;
}

__global__ void scatter_kernel(const int* __restrict__ ei,
                               const float* __restrict__ ew, int E) {
    int gt = blockIdx.x * blockDim.x + threadIdx.x;
    if (gt < MAX_BLOCKS) g_pack[gt] = 0ULL;  // reset lookback state (scan done)
    if (gt >= E) return;
    int r = ei[gt], c = ei[E + gt];
    float nrm = -g_dis[r] * ew[gt] * g_dis[c];
    int p = atomicAdd(&g_cursor[c], 1);
    g_edge[p] = make_int2(r, __float_as_int(nrm));
}

// warp-per-node gather propagation; float2 features, int2 edge meta, unroll 4.
// pass 0 also converts the node's own x row into A columns [0,64) (hi/lo).
__global__ void prop_kernel(const float* __restrict__ xin, int pass, int n) {
    int warp = (blockIdx.x * blockDim.x + threadIdx.x) >> 5;
    int lane = threadIdx.x & 31;
    if (warp >= n) return;
    const float2* __restrict__ feat =
        reinterpret_cast<const float2*>(pass ? g_tx1 : xin);
    int s = g_rowptr[warp], e = g_rowptr[warp + 1];
    float a0 = 0.0f, a1 = 0.0f;
    int p = s;
    for (; p + 3 < e; p += 4) {
        int2 e0 = __ldg(&g_edge[p]);
        int2 e1 = __ldg(&g_edge[p + 1]);
        int2 e2 = __ldg(&g_edge[p + 2]);
        int2 e3 = __ldg(&g_edge[p + 3]);
        float2 f0 = __ldg(&feat[e0.x * 32 + lane]);
        float2 f1 = __ldg(&feat[e1.x * 32 + lane]);
        float2 f2 = __ldg(&feat[e2.x * 32 + lane]);
        float2 f3 = __ldg(&feat[e3.x * 32 + lane]);
        float w0 = __int_as_float(e0.y), w1 = __int_as_float(e1.y);
        float w2 = __int_as_float(e2.y), w3 = __int_as_float(e3.y);
        a0 += w0 * f0.x; a1 += w0 * f0.y;
        a0 += w1 * f1.x; a1 += w1 * f1.y;
        a0 += w2 * f2.x; a1 += w2 * f2.y;
        a0 += w3 * f3.x; a1 += w3 * f3.y;
    }
    for (; p < e; p++) {
        int2 e0 = __ldg(&g_edge[p]);
        float2 f0 = __ldg(&feat[e0.x * 32 + lane]);
        float w0 = __int_as_float(e0.y);
        a0 += w0 * f0.x; a1 += w0 * f0.y;
    }
    if (pass == 0) {   // tx1 fp32 needed by pass 1 (same float2 layout)
        reinterpret_cast<float2*>(g_tx1)[warp * 32 + lane] = make_float2(a0, a1);
        // fused convert of own x row -> A cols [0,64)
        float2 xv = __ldg(&feat[warp * 32 + lane]);
        __nv_bfloat16 xh0 = __float2bfloat16_rn(xv.x);
        __nv_bfloat16 xh1 = __float2bfloat16_rn(xv.y);
        __nv_bfloat162 xhi; xhi.x = xh0; xhi.y = xh1;
        __nv_bfloat162 xlo;
        xlo.x = __float2bfloat16_rn(xv.x - __bfloat162float(xh0));
        xlo.y = __float2bfloat16_rn(xv.y - __bfloat162float(xh1));
        *reinterpret_cast<__nv_bfloat162*>(g_Ahi + warp * KTOT + 2 * lane) = xhi;
        *reinterpret_cast<__nv_bfloat162*>(g_Alo + warp * KTOT + 2 * lane) = xlo;
    }
    int cbase = pass ? 128 : 64;
    __nv_bfloat16 h0 = __float2bfloat16_rn(a0);
    __nv_bfloat16 h1 = __float2bfloat16_rn(a1);
    __nv_bfloat162 hi; hi.x = h0; hi.y = h1;
    __nv_bfloat162 lo;
    lo.x = __float2bfloat16_rn(a0 - __bfloat162float(h0));
    lo.y = __float2bfloat16_rn(a1 - __bfloat162float(h1));
    *reinterpret_cast<__nv_bfloat162*>(g_Ahi + warp * KTOT + cbase + 2 * lane) = hi;
    *reinterpret_cast<__nv_bfloat162*>(g_Alo + warp * KTOT + cbase + 2 * lane) = lo;
}

// build combined weights -> bf16 hi/lo B stored [n][k] ; biases
__global__ void weights_kernel(const float* __restrict__ Wxz,
                               const float* __restrict__ bxz,
                               const float* __restrict__ bhz,
                               const float* __restrict__ Wxh,
                               const float* __restrict__ bxh,
                               const float* __restrict__ bhh) {
    int idx = blockIdx.x * blockDim.x + threadIdx.x;
    if (idx < KTOT * NOUT) {
        int k = idx / NOUT, nn = idx % NOUT;
        int seg = k / 64, i = k % 64;
        const float* W = (nn < 64) ? Wxz : Wxh;
        int j = (nn < 64) ? nn : (nn - 64);
        float v;
        if (seg == 0)      v = W[(0 * 64 + i) * 64 + j] - W[(2 * 64 + i) * 64 + j];
        else if (seg == 1) v = W[(1 * 64 + i) * 64 + j];
        else               v = 2.0f * W[(2 * 64 + i) * 64 + j];
        __nv_bfloat16 hi = __float2bfloat16_rn(v);
        float lo = v - __bfloat162float(hi);
        g_Bhi[nn * KTOT + k] = hi;
        g_Blo[nn * KTOT + k] = __float2bfloat16_rn(lo);
    }
    if (blockIdx.x == 0 && threadIdx.x < F) {
        g_bz[threadIdx.x] = bxz[threadIdx.x] + bhz[threadIdx.x];
        g_bh[threadIdx.x] = bxh[threadIdx.x] + bhh[threadIdx.x];
    }
}

__device__ __forceinline__ float sigm(float v) { return 1.0f / (1.0f + expf(-v)); }

// ---------------- HMMA bf16x3 GEMM + fused GRU/head epilogue ----------------
// SMEM rows padded to 400B (rotates 16B per row across banks -> conflict-free LDSM)
#define SA_B 400
#define SM_AHI 0
#define SM_ALO 51200
#define SM_BHI 102400
#define SM_BLO 153600
#define GSM_TOTAL 204800
#define SC 132            // C f32 row stride

__global__ __launch_bounds__(256, 1)
void gemm_kernel(const float* __restrict__ Wlin,
                 const float* __restrict__ blin,
                 float* __restrict__ out, int n) {
    extern __shared__ char smem[];
    uint32_t sbase = smem_u32(smem);
    int tid = threadIdx.x, lane = tid & 31, wid = tid >> 5;
    int row0 = blockIdx.x * 128;

    // stage A (hi/lo) and B (hi/lo) into padded SMEM
    for (int it = tid; it < 3072; it += 256) {
        int r = it / 24, c = it % 24;
        int rg = row0 + r;
        uint4 vh = make_uint4(0, 0, 0, 0), vl = make_uint4(0, 0, 0, 0);
        if (rg < n) {
            vh = *reinterpret_cast<const uint4*>(g_Ahi + rg * KTOT + c * 8);
            vl = *reinterpret_cast<const uint4*>(g_Alo + rg * KTOT + c * 8);
        }
        *reinterpret_cast<uint4*>(smem + SM_AHI + r * SA_B + c * 16) = vh;
        *reinterpret_cast<uint4*>(smem + SM_ALO + r * SA_B + c * 16) = vl;
        uint4 bh = *reinterpret_cast<const uint4*>(g_Bhi + r * KTOT + c * 8);
        uint4 bl = *reinterpret_cast<const uint4*>(g_Blo + r * KTOT + c * 8);
        *reinterpret_cast<uint4*>(smem + SM_BHI + r * SA_B + c * 16) = bh;
        *reinterpret_cast<uint4*>(smem + SM_BLO + r * SA_B + c * 16) = bl;
    }
    __syncthreads();

    // warp tiling: 4x2 warps, each 32(M) x 64(N)
    int m0 = (wid & 3) * 32, n0 = (wid >> 2) * 64;
    int a_r = (lane & 7) + ((lane >> 3) & 1) * 8;
    int a_k = ((lane >> 4) & 1) * 8;
    int b_r = (lane & 7) + ((lane >> 4) & 1) * 8;
    int b_k = ((lane >> 3) & 1) * 8;

    float acc[2][8][4];
    #pragma unroll
    for (int i = 0; i < 2; i++)
        #pragma unroll
        for (int j = 0; j < 8; j++)
            #pragma unroll
            for (int q = 0; q < 4; q++) acc[i][j][q] = 0.0f;

    #pragma unroll
    for (int pass = 0; pass < 3; pass++) {
        uint32_t abase = sbase + ((pass == 2) ? SM_ALO : SM_AHI);
        uint32_t bbase = sbase + ((pass == 1) ? SM_BLO : SM_BHI);
        uint32_t aaddr0 = abase + (uint32_t)((m0 + a_r) * SA_B + a_k * 2);
        uint32_t aaddr1 = aaddr0 + 16 * SA_B;
        uint32_t baddr0 = bbase + (uint32_t)((n0 + b_r) * SA_B + b_k * 2);
        #pragma unroll
        for (int k = 0; k < KTOT; k += 16) {
            uint32_t a0[4], a1[4], bb[4][4];
            ldsm4(a0, aaddr0 + k * 2);
            ldsm4(a1, aaddr1 + k * 2);
            #pragma unroll
            for (int g = 0; g < 4; g++)
                ldsm4(bb[g], baddr0 + (uint32_t)(g * 16 * SA_B) + k * 2);
            #pragma unroll
            for (int g = 0; g < 4; g++) {
                mma_bf16(acc[0][2 * g],     a0, bb[g][0], bb[g][1]);
                mma_bf16(acc[0][2 * g + 1], a0, bb[g][2], bb[g][3]);
                mma_bf16(acc[1][2 * g],     a1, bb[g][0], bb[g][1]);
                mma_bf16(acc[1][2 * g + 1], a1, bb[g][2], bb[g][3]);
            }
        }
    }
    __syncthreads();

    // write C fragments to SMEM (reuses A region; 128 x 132 f32 = 67.6 KB)
    float* C = reinterpret_cast<float*>(smem);
    #pragma unroll
    for (int ms = 0; ms < 2; ms++) {
        #pragma unroll
        for (int ns = 0; ns < 8; ns++) {
            int r = m0 + ms * 16 + (lane >> 2);
            int c = n0 + ns * 8 + (lane & 3) * 2;
            float2 v0 = make_float2(acc[ms][ns][0], acc[ms][ns][1]);
            float2 v1 = make_float2(acc[ms][ns][2], acc[ms][ns][3]);
            *reinterpret_cast<float2*>(C + r * SC + c) = v0;
            *reinterpret_cast<float2*>(C + (r + 8) * SC + c) = v1;
        }
    }
    __syncthreads();

    // fused epilogue: one thread per row
    if (tid < 128) {
        int r = row0 + tid;
        const float* Cr = C + tid * SC;
        float s0 = 0.0f, s1 = 0.0f;
        #pragma unroll 4
        for (int j = 0; j < 64; j++) {
            float z = sigm(Cr[j] + __ldg(&g_bz[j]));
            float t = tanhf(Cr[j + 64] + __ldg(&g_bh[j]));
            float u = tanhf((1.0f - z) * t);
            s0 += u * __ldg(&Wlin[j * 2 + 0]);
            s1 += u * __ldg(&Wlin[j * 2 + 1]);
        }
        if (r < n) {
            out[r * 2 + 0] = sigm(s0 + __ldg(&blin[0]));
            out[r * 2 + 1] = sigm(s1 + __ldg(&blin[1]));
        }
    }
}

// ---------------- launch ----------------
extern "C" void kernel_launch(void* const* d_in, const int* in_sizes, int n_in,
                              void* d_out, int out_size) {
    const float* x    = (const float*)d_in[0];
    const int*   ei   = (const int*)d_in[1];
    const float* ew   = (const float*)d_in[2];
    const float* Wxz  = (const float*)d_in[3];
    const float* bxz  = (const float*)d_in[4];
    const float* bhz  = (const float*)d_in[6];
    const float* Wxh  = (const float*)d_in[11];
    const float* bxh  = (const float*)d_in[12];
    const float* bhh  = (const float*)d_in[14];
    const float* Wlin = (const float*)d_in[15];
    const float* blin = (const float*)d_in[16];
    float* out = (float*)d_out;

    int n = in_sizes[0] / F;       // 50000
    int E = in_sizes[2];           // 800000
    int nb = (n + SCAN_TILE - 1) / SCAN_TILE;

    cudaFuncSetAttribute(gemm_kernel, cudaFuncAttributeMaxDynamicSharedMemorySize, GSM_TOTAL);

    edge_pass1_kernel<<<(E + 255) / 256, 256>>>(ei, ew, E);
    scan_kernel<<<nb, SCAN_TILE>>>(n, nb);
    scatter_kernel<<<(E + 255) / 256, 256>>>(ei, ew, E);

    int prop_blocks = (n * 32 + 255) / 256;
    prop_kernel<<<prop_blocks, 256>>>(x, 0, n);
    prop_kernel<<<prop_blocks, 256>>>(x, 1, n);

    weights_kernel<<<(KTOT * NOUT + 255) / 256, 256>>>(Wxz, bxz, bhz, Wxh, bxh, bhh);
    gemm_kernel<<<(n + 127) / 128, 256, GSM_TOTAL>>>(Wlin, blin, out, n);
    (void)n_in; (void)out_size;
}

// round 10
// speedup vs baseline: 1.3662x; 1.3662x over previous
#include <cuda_runtime.h>
#include <cuda_bf16.h>
#include <cstdint>
#include <math.h>

#define N_NODES 50000
#define N_EDGES 800000
#define F 64          // F_IN == F_HID
#define KTOT 192      // x | tx1 | y
#define NOUT 128      // z (64) | h (64)
#define SCAN_TILE 1024
#define MAX_BLOCKS ((N_NODES + SCAN_TILE - 1) / SCAN_TILE + 1)

// ---------------- device scratch (allocation-free) ----------------
__device__ float g_deg[N_NODES];
__device__ float g_dis[N_NODES];
__device__ int   g_count[N_NODES];
__device__ int   g_rowptr[N_NODES + 1];
__device__ int   g_cursor[N_NODES];
__device__ int   g_bsum[MAX_BLOCKS];
__device__ __align__(16) int2 g_edge[N_EDGES];      // (src, norm-bits)
__device__ __align__(16) float g_tx1[N_NODES * F];
__device__ __align__(16) __nv_bfloat16 g_Ahi[N_NODES * KTOT];
__device__ __align__(16) __nv_bfloat16 g_Alo[N_NODES * KTOT];
__device__ __align__(16) __nv_bfloat16 g_Bhi[NOUT * KTOT];   // [n][k], k-contiguous
__device__ __align__(16) __nv_bfloat16 g_Blo[NOUT * KTOT];
__device__ float g_bz[F];
__device__ float g_bh[F];

// ---------------- PTX helpers ----------------
__device__ __forceinline__ uint32_t smem_u32(const void* p) {
    uint32_t a;
    asm("{ .reg .u64 t; cvta.to.shared.u64 t, %1; cvt.u32.u64 %0, t; }" : "=r"(a) : "l"(p));
    return a;
}
__device__ __forceinline__ void ldsm4(uint32_t (&d)[4], uint32_t addr) {
    asm volatile("ldmatrix.sync.aligned.m8n8.x4.shared.b16 {%0,%1,%2,%3}, [%4];\n"
                 : "=r"(d[0]), "=r"(d[1]), "=r"(d[2]), "=r"(d[3]) : "r"(addr));
}
__device__ __forceinline__ void mma_bf16(float (&c)[4], const uint32_t (&a)[4],
                                         uint32_t b0, uint32_t b1) {
    asm volatile(
        "mma.sync.aligned.m16n8k16.row.col.f32.bf16.bf16.f32 "
        "{%0,%1,%2,%3}, {%4,%5,%6,%7}, {%8,%9}, {%0,%1,%2,%3};\n"
        : "+f"(c[0]), "+f"(c[1]), "+f"(c[2]), "+f"(c[3])
        : "r"(a[0]), "r"(a[1]), "r"(a[2]), "r"(a[3]), "r"(b0), "r"(b1));
}

// ---------------- kernels ----------------

__global__ void init_kernel(int n) {
    int i = blockIdx.x * blockDim.x + threadIdx.x;
    if (i < n) { g_deg[i] = 0.0f; g_count[i] = 0; }
}

__global__ void edge_pass1_kernel(const int* __restrict__ ei,
                                  const float* __restrict__ ew, int E) {
    int e = blockIdx.x * blockDim.x + threadIdx.x;
    if (e >= E) return;
    atomicAdd(&g_deg[ei[e]], ew[e]);
    atomicAdd(&g_count[ei[E + e]], 1);
}

// Phase 1: per-1024-tile local exclusive scan; tile total -> g_bsum
__global__ void scan_phase1_kernel(int n) {
    __shared__ int warp_sums[32];
    int tid = threadIdx.x, lane = tid & 31, wid = tid >> 5;
    int i = blockIdx.x * SCAN_TILE + tid;
    int v = (i < n) ? g_count[i] : 0;
    int incl = v;
    #pragma unroll
    for (int o = 1; o < 32; o <<= 1) {
        int t = __shfl_up_sync(0xffffffffu, incl, o);
        if (lane >= o) incl += t;
    }
    if (lane == 31) warp_sums[wid] = incl;
    __syncthreads();
    if (wid == 0) {
        int s = warp_sums[lane];
        int sincl = s;
        #pragma unroll
        for (int o = 1; o < 32; o <<= 1) {
            int t = __shfl_up_sync(0xffffffffu, sincl, o);
            if (lane >= o) sincl += t;
        }
        warp_sums[lane] = sincl - s;
        if (lane == 31) g_bsum[blockIdx.x] = sincl;
    }
    __syncthreads();
    int excl = warp_sums[wid] + incl - v;
    if (i < n) g_rowptr[i] = excl;
}

// Phase 2 (fused into phase 3): each 256-block computes its tile offset by
// summing g_bsum[j < tile] (nb <= 64, plain reads, no polling). Also fuses
// dis computation and cursor init; rowptr[n] = E.
__global__ void scan_phase3_kernel(int n, int nb, int E) {
    __shared__ int s_off;
    int i = blockIdx.x * blockDim.x + threadIdx.x;
    int t = (int)((blockIdx.x * blockDim.x) >> 10);   // 1024-tile index of this block
    if (threadIdx.x < 32) {
        int lane = threadIdx.x;
        int v0 = (lane < t && lane < nb) ? g_bsum[lane] : 0;
        int v1 = (lane + 32 < t && lane + 32 < nb) ? g_bsum[lane + 32] : 0;
        int s = v0 + v1;
        #pragma unroll
        for (int o = 16; o > 0; o >>= 1) s += __shfl_xor_sync(0xffffffffu, s, o);
        if (lane == 0) s_off = s;
    }
    __syncthreads();
    if (i >= n) return;
    int val = g_rowptr[i] + s_off;
    g_rowptr[i] = val;
    g_cursor[i] = val;
    float d = g_deg[i];
    g_dis[i] = (d > 0.0f) ? rsqrtf(d) : 0.0f;
    if (i == 0) g_rowptr[n] = E;
}

__global__ void scatter_kernel(const int* __restrict__ ei,
                               const float* __restrict__ ew, int E) {
    int e = blockIdx.x * blockDim.x + threadIdx.x;
    if (e >= E) return;
    int r = ei[e], c = ei[E + e];
    float nrm = -g_dis[r] * ew[e] * g_dis[c];
    int p = atomicAdd(&g_cursor[c], 1);
    g_edge[p] = make_int2(r, __float_as_int(nrm));
}

// warp-per-node gather propagation; float2 features, int2 edge meta, unroll 8.
// pass 0 also converts the node's own x row into A columns [0,64) (hi/lo).
__global__ void prop_kernel(const float* __restrict__ xin, int pass, int n) {
    int warp = (blockIdx.x * blockDim.x + threadIdx.x) >> 5;
    int lane = threadIdx.x & 31;
    if (warp >= n) return;
    const float2* __restrict__ feat =
        reinterpret_cast<const float2*>(pass ? g_tx1 : xin);
    int s = g_rowptr[warp], e = g_rowptr[warp + 1];
    float a0 = 0.0f, a1 = 0.0f;
    int p = s;
    for (; p + 7 < e; p += 8) {
        int2 em[8];
        float2 f[8];
        #pragma unroll
        for (int q = 0; q < 8; q++) em[q] = __ldg(&g_edge[p + q]);
        #pragma unroll
        for (int q = 0; q < 8; q++) f[q] = __ldg(&feat[em[q].x * 32 + lane]);
        #pragma unroll
        for (int q = 0; q < 8; q++) {
            float w = __int_as_float(em[q].y);
            a0 += w * f[q].x;
            a1 += w * f[q].y;
        }
    }
    for (; p < e; p++) {
        int2 e0 = __ldg(&g_edge[p]);
        float2 f0 = __ldg(&feat[e0.x * 32 + lane]);
        float w0 = __int_as_float(e0.y);
        a0 += w0 * f0.x; a1 += w0 * f0.y;
    }
    if (pass == 0) {   // tx1 fp32 needed by pass 1 (same float2 layout)
        reinterpret_cast<float2*>(g_tx1)[warp * 32 + lane] = make_float2(a0, a1);
        // fused convert of own x row -> A cols [0,64)
        float2 xv = __ldg(&feat[warp * 32 + lane]);
        __nv_bfloat16 xh0 = __float2bfloat16_rn(xv.x);
        __nv_bfloat16 xh1 = __float2bfloat16_rn(xv.y);
        __nv_bfloat162 xhi; xhi.x = xh0; xhi.y = xh1;
        __nv_bfloat162 xlo;
        xlo.x = __float2bfloat16_rn(xv.x - __bfloat162float(xh0));
        xlo.y = __float2bfloat16_rn(xv.y - __bfloat162float(xh1));
        *reinterpret_cast<__nv_bfloat162*>(g_Ahi + warp * KTOT + 2 * lane) = xhi;
        *reinterpret_cast<__nv_bfloat162*>(g_Alo + warp * KTOT + 2 * lane) = xlo;
    }
    int cbase = pass ? 128 : 64;
    __nv_bfloat16 h0 = __float2bfloat16_rn(a0);
    __nv_bfloat16 h1 = __float2bfloat16_rn(a1);
    __nv_bfloat162 hi; hi.x = h0; hi.y = h1;
    __nv_bfloat162 lo;
    lo.x = __float2bfloat16_rn(a0 - __bfloat162float(h0));
    lo.y = __float2bfloat16_rn(a1 - __bfloat162float(h1));
    *reinterpret_cast<__nv_bfloat162*>(g_Ahi + warp * KTOT + cbase + 2 * lane) = hi;
    *reinterpret_cast<__nv_bfloat162*>(g_Alo + warp * KTOT + cbase + 2 * lane) = lo;
}

// build combined weights -> bf16 hi/lo B stored [n][k] ; biases
__global__ void weights_kernel(const float* __restrict__ Wxz,
                               const float* __restrict__ bxz,
                               const float* __restrict__ bhz,
                               const float* __restrict__ Wxh,
                               const float* __restrict__ bxh,
                               const float* __restrict__ bhh) {
    int idx = blockIdx.x * blockDim.x + threadIdx.x;
    if (idx < KTOT * NOUT) {
        int k = idx / NOUT, nn = idx % NOUT;
        int seg = k / 64, i = k % 64;
        const float* W = (nn < 64) ? Wxz : Wxh;
        int j = (nn < 64) ? nn : (nn - 64);
        float v;
        if (seg == 0)      v = W[(0 * 64 + i) * 64 + j] - W[(2 * 64 + i) * 64 + j];
        else if (seg == 1) v = W[(1 * 64 + i) * 64 + j];
        else               v = 2.0f * W[(2 * 64 + i) * 64 + j];
        __nv_bfloat16 hi = __float2bfloat16_rn(v);
        float lo = v - __bfloat162float(hi);
        g_Bhi[nn * KTOT + k] = hi;
        g_Blo[nn * KTOT + k] = __float2bfloat16_rn(lo);
    }
    if (blockIdx.x == 0 && threadIdx.x < F) {
        g_bz[threadIdx.x] = bxz[threadIdx.x] + bhz[threadIdx.x];
        g_bh[threadIdx.x] = bxh[threadIdx.x] + bhh[threadIdx.x];
    }
}

__device__ __forceinline__ float sigm(float v) { return 1.0f / (1.0f + expf(-v)); }

// ---------------- HMMA bf16x3 GEMM + fused GRU/head epilogue ----------------
// SMEM rows padded to 400B (rotates 16B per row across banks -> conflict-free LDSM)
#define SA_B 400
#define SM_AHI 0
#define SM_ALO 51200
#define SM_BHI 102400
#define SM_BLO 153600
#define GSM_TOTAL 204800
#define SC 132            // C f32 row stride

__global__ __launch_bounds__(256, 1)
void gemm_kernel(const float* __restrict__ Wlin,
                 const float* __restrict__ blin,
                 float* __restrict__ out, int n) {
    extern __shared__ char smem[];
    uint32_t sbase = smem_u32(smem);
    int tid = threadIdx.x, lane = tid & 31, wid = tid >> 5;
    int row0 = blockIdx.x * 128;

    // stage A (hi/lo) and B (hi/lo) into padded SMEM
    for (int it = tid; it < 3072; it += 256) {
        int r = it / 24, c = it % 24;
        int rg = row0 + r;
        uint4 vh = make_uint4(0, 0, 0, 0), vl = make_uint4(0, 0, 0, 0);
        if (rg < n) {
            vh = *reinterpret_cast<const uint4*>(g_Ahi + rg * KTOT + c * 8);
            vl = *reinterpret_cast<const uint4*>(g_Alo + rg * KTOT + c * 8);
        }
        *reinterpret_cast<uint4*>(smem + SM_AHI + r * SA_B + c * 16) = vh;
        *reinterpret_cast<uint4*>(smem + SM_ALO + r * SA_B + c * 16) = vl;
        uint4 bh = *reinterpret_cast<const uint4*>(g_Bhi + r * KTOT + c * 8);
        uint4 bl = *reinterpret_cast<const uint4*>(g_Blo + r * KTOT + c * 8);
        *reinterpret_cast<uint4*>(smem + SM_BHI + r * SA_B + c * 16) = bh;
        *reinterpret_cast<uint4*>(smem + SM_BLO + r * SA_B + c * 16) = bl;
    }
    __syncthreads();

    // warp tiling: 4x2 warps, each 32(M) x 64(N)
    int m0 = (wid & 3) * 32, n0 = (wid >> 2) * 64;
    int a_r = (lane & 7) + ((lane >> 3) & 1) * 8;
    int a_k = ((lane >> 4) & 1) * 8;
    int b_r = (lane & 7) + ((lane >> 4) & 1) * 8;
    int b_k = ((lane >> 3) & 1) * 8;

    float acc[2][8][4];
    #pragma unroll
    for (int i = 0; i < 2; i++)
        #pragma unroll
        for (int j = 0; j < 8; j++)
            #pragma unroll
            for (int q = 0; q < 4; q++) acc[i][j][q] = 0.0f;

    #pragma unroll
    for (int pass = 0; pass < 3; pass++) {
        uint32_t abase = sbase + ((pass == 2) ? SM_ALO : SM_AHI);
        uint32_t bbase = sbase + ((pass == 1) ? SM_BLO : SM_BHI);
        uint32_t aaddr0 = abase + (uint32_t)((m0 + a_r) * SA_B + a_k * 2);
        uint32_t aaddr1 = aaddr0 + 16 * SA_B;
        uint32_t baddr0 = bbase + (uint32_t)((n0 + b_r) * SA_B + b_k * 2);
        #pragma unroll
        for (int k = 0; k < KTOT; k += 16) {
            uint32_t a0[4], a1[4], bb[4][4];
            ldsm4(a0, aaddr0 + k * 2);
            ldsm4(a1, aaddr1 + k * 2);
            #pragma unroll
            for (int g = 0; g < 4; g++)
                ldsm4(bb[g], baddr0 + (uint32_t)(g * 16 * SA_B) + k * 2);
            #pragma unroll
            for (int g = 0; g < 4; g++) {
                mma_bf16(acc[0][2 * g],     a0, bb[g][0], bb[g][1]);
                mma_bf16(acc[0][2 * g + 1], a0, bb[g][2], bb[g][3]);
                mma_bf16(acc[1][2 * g],     a1, bb[g][0], bb[g][1]);
                mma_bf16(acc[1][2 * g + 1], a1, bb[g][2], bb[g][3]);
            }
        }
    }
    __syncthreads();

    // write C fragments to SMEM (reuses A region; 128 x 132 f32 = 67.6 KB)
    float* C = reinterpret_cast<float*>(smem);
    #pragma unroll
    for (int ms = 0; ms < 2; ms++) {
        #pragma unroll
        for (int ns = 0; ns < 8; ns++) {
            int r = m0 + ms * 16 + (lane >> 2);
            int c = n0 + ns * 8 + (lane & 3) * 2;
            float2 v0 = make_float2(acc[ms][ns][0], acc[ms][ns][1]);
            float2 v1 = make_float2(acc[ms][ns][2], acc[ms][ns][3]);
            *reinterpret_cast<float2*>(C + r * SC + c) = v0;
            *reinterpret_cast<float2*>(C + (r + 8) * SC + c) = v1;
        }
    }
    __syncthreads();

    // fused epilogue: one thread per row
    if (tid < 128) {
        int r = row0 + tid;
        const float* Cr = C + tid * SC;
        float s0 = 0.0f, s1 = 0.0f;
        #pragma unroll 4
        for (int j = 0; j < 64; j++) {
            float z = sigm(Cr[j] + __ldg(&g_bz[j]));
            float t = tanhf(Cr[j + 64] + __ldg(&g_bh[j]));
            float u = tanhf((1.0f - z) * t);
            s0 += u * __ldg(&Wlin[j * 2 + 0]);
            s1 += u * __ldg(&Wlin[j * 2 + 1]);
        }
        if (r < n) {
            out[r * 2 + 0] = sigm(s0 + __ldg(&blin[0]));
            out[r * 2 + 1] = sigm(s1 + __ldg(&blin[1]));
        }
    }
}

// ---------------- launch ----------------
extern "C" void kernel_launch(void* const* d_in, const int* in_sizes, int n_in,
                              void* d_out, int out_size) {
    const float* x    = (const float*)d_in[0];
    const int*   ei   = (const int*)d_in[1];
    const float* ew   = (const float*)d_in[2];
    const float* Wxz  = (const float*)d_in[3];
    const float* bxz  = (const float*)d_in[4];
    const float* bhz  = (const float*)d_in[6];
    const float* Wxh  = (const float*)d_in[11];
    const float* bxh  = (const float*)d_in[12];
    const float* bhh  = (const float*)d_in[14];
    const float* Wlin = (const float*)d_in[15];
    const float* blin = (const float*)d_in[16];
    float* out = (float*)d_out;

    int n = in_sizes[0] / F;       // 50000
    int E = in_sizes[2];           // 800000
    int nb = (n + SCAN_TILE - 1) / SCAN_TILE;

    cudaFuncSetAttribute(gemm_kernel, cudaFuncAttributeMaxDynamicSharedMemorySize, GSM_TOTAL);

    init_kernel<<<(n + 255) / 256, 256>>>(n);
    edge_pass1_kernel<<<(E + 255) / 256, 256>>>(ei, ew, E);
    scan_phase1_kernel<<<nb, SCAN_TILE>>>(n);
    scan_phase3_kernel<<<(n + 255) / 256, 256>>>(n, nb, E);
    scatter_kernel<<<(E + 255) / 256, 256>>>(ei, ew, E);

    int prop_blocks = (n * 32 + 255) / 256;
    prop_kernel<<<prop_blocks, 256>>>(x, 0, n);
    prop_kernel<<<prop_blocks, 256>>>(x, 1, n);

    weights_kernel<<<(KTOT * NOUT + 255) / 256, 256>>>(Wxz, bxz, bhz, Wxh, bxh, bhh);
    gemm_kernel<<<(n + 127) / 128, 256, GSM_TOTAL>>>(Wlin, blin, out, n);
    (void)n_in; (void)out_size;
}

// round 11
// speedup vs baseline: 1.3793x; 1.0096x over previous
#include <cuda_runtime.h>
#include <cuda_bf16.h>
#include <cstdint>
#include <math.h>

#define N_NODES 50000
#define N_EDGES 800000
#define F 64          // F_IN == F_HID
#define KTOT 192      // x | tx1 | y
#define NOUT 128      // z (64) | h (64)
#define SCAN_TILE 1024
#define MAX_BLOCKS ((N_NODES + SCAN_TILE - 1) / SCAN_TILE + 1)

// ---------------- device scratch (allocation-free) ----------------
// Self-clean invariant: scan_phase1 zeroes g_count, scan_phase3 zeroes g_deg,
// so every kernel_launch call leaves them zeroed for the next call.
__device__ float g_deg[N_NODES];
__device__ float g_dis[N_NODES];
__device__ int   g_count[N_NODES];
__device__ int   g_rowptr[N_NODES + 1];
__device__ int   g_cursor[N_NODES];
__device__ int   g_bsum[MAX_BLOCKS];
__device__ __align__(16) int2 g_edge[N_EDGES];      // (src, norm-bits)
__device__ __align__(16) float g_tx1[N_NODES * F];
__device__ __align__(16) __nv_bfloat16 g_Ahi[N_NODES * KTOT];
__device__ __align__(16) __nv_bfloat16 g_Alo[N_NODES * KTOT];
__device__ __align__(16) __nv_bfloat16 g_Bhi[NOUT * KTOT];   // [n][k], k-contiguous
__device__ __align__(16) __nv_bfloat16 g_Blo[NOUT * KTOT];
__device__ float g_bz[F];
__device__ float g_bh[F];

// ---------------- PTX helpers ----------------
__device__ __forceinline__ uint32_t smem_u32(const void* p) {
    uint32_t a;
    asm("{ .reg .u64 t; cvta.to.shared.u64 t, %1; cvt.u32.u64 %0, t; }" : "=r"(a) : "l"(p));
    return a;
}
__device__ __forceinline__ void ldsm4(uint32_t (&d)[4], uint32_t addr) {
    asm volatile("ldmatrix.sync.aligned.m8n8.x4.shared.b16 {%0,%1,%2,%3}, [%4];\n"
                 : "=r"(d[0]), "=r"(d[1]), "=r"(d[2]), "=r"(d[3]) : "r"(addr));
}
__device__ __forceinline__ void mma_bf16(float (&c)[4], const uint32_t (&a)[4],
                                         uint32_t b0, uint32_t b1) {
    asm volatile(
        "mma.sync.aligned.m16n8k16.row.col.f32.bf16.bf16.f32 "
        "{%0,%1,%2,%3}, {%4,%5,%6,%7}, {%8,%9}, {%0,%1,%2,%3};\n"
        : "+f"(c[0]), "+f"(c[1]), "+f"(c[2]), "+f"(c[3])
        : "r"(a[0]), "r"(a[1]), "r"(a[2]), "r"(a[3]), "r"(b0), "r"(b1));
}

// ---------------- kernels ----------------

__global__ void edge_pass1_kernel(const int* __restrict__ ei,
                                  const float* __restrict__ ew, int E) {
    int e = blockIdx.x * blockDim.x + threadIdx.x;
    if (e >= E) return;
    atomicAdd(&g_deg[ei[e]], ew[e]);
    atomicAdd(&g_count[ei[E + e]], 1);
}

// Phase 1: per-1024-tile local exclusive scan; tile total -> g_bsum.
// Also zeroes g_count (self-clean for next replay).
__global__ void scan_phase1_kernel(int n) {
    __shared__ int warp_sums[32];
    int tid = threadIdx.x, lane = tid & 31, wid = tid >> 5;
    int i = blockIdx.x * SCAN_TILE + tid;
    int v = (i < n) ? g_count[i] : 0;
    int incl = v;
    #pragma unroll
    for (int o = 1; o < 32; o <<= 1) {
        int t = __shfl_up_sync(0xffffffffu, incl, o);
        if (lane >= o) incl += t;
    }
    if (lane == 31) warp_sums[wid] = incl;
    __syncthreads();
    if (wid == 0) {
        int s = warp_sums[lane];
        int sincl = s;
        #pragma unroll
        for (int o = 1; o < 32; o <<= 1) {
            int t = __shfl_up_sync(0xffffffffu, sincl, o);
            if (lane >= o) sincl += t;
        }
        warp_sums[lane] = sincl - s;
        if (lane == 31) g_bsum[blockIdx.x] = sincl;
    }
    __syncthreads();
    int excl = warp_sums[wid] + incl - v;
    if (i < n) {
        g_rowptr[i] = excl;
        g_count[i] = 0;          // self-clean
    }
}

// Phase 3: one 1024-block per tile (t = blockIdx.x). Adds tile offset
// (sum of g_bsum[j<t], warp-computed, no polling), fills cursor, computes dis,
// zeroes g_deg; rowptr[n] = E.
__global__ void scan_phase3_kernel(int n, int nb, int E) {
    __shared__ int s_off;
    int t = blockIdx.x;
    int i = t * SCAN_TILE + threadIdx.x;
    if (threadIdx.x < 32) {
        int lane = threadIdx.x;
        int v0 = (lane < t) ? g_bsum[lane] : 0;
        int v1 = (lane + 32 < t) ? g_bsum[lane + 32] : 0;
        int s = v0 + v1;
        #pragma unroll
        for (int o = 16; o > 0; o >>= 1) s += __shfl_xor_sync(0xffffffffu, s, o);
        if (lane == 0) s_off = s;
    }
    __syncthreads();
    if (i >= n) return;
    int val = g_rowptr[i] + s_off;
    g_rowptr[i] = val;
    g_cursor[i] = val;
    float d = g_deg[i];
    g_dis[i] = (d > 0.0f) ? rsqrtf(d) : 0.0f;
    g_deg[i] = 0.0f;             // self-clean
    if (i == 0) g_rowptr[n] = E;
}

__global__ void scatter_kernel(const int* __restrict__ ei,
                               const float* __restrict__ ew, int E) {
    int e = blockIdx.x * blockDim.x + threadIdx.x;
    if (e >= E) return;
    int r = ei[e], c = ei[E + e];
    float nrm = -g_dis[r] * ew[e] * g_dis[c];
    int p = atomicAdd(&g_cursor[c], 1);
    g_edge[p] = make_int2(r, __float_as_int(nrm));
}

// warp-per-node gather propagation.
// Edge meta loaded one-edge-per-lane (register-resident, coalesced), then
// shfl-broadcast per edge -> feature loads depend only on a shuffle, 8 in flight.
// pass 0 also converts the node's own x row into A columns [0,64) (hi/lo).
__global__ void prop_kernel(const float* __restrict__ xin, int pass, int n) {
    int warp = (blockIdx.x * blockDim.x + threadIdx.x) >> 5;
    int lane = threadIdx.x & 31;
    if (warp >= n) return;
    const float2* __restrict__ feat =
        reinterpret_cast<const float2*>(pass ? g_tx1 : xin);
    int s = g_rowptr[warp], e = g_rowptr[warp + 1];
    float a0 = 0.0f, a1 = 0.0f;
    for (int base = s; base < e; base += 32) {
        int idx = base + lane;
        int2 m = (idx < e) ? __ldg(&g_edge[idx]) : make_int2(0, 0);
        int cnt = min(32, e - base);
        for (int q0 = 0; q0 < cnt; q0 += 8) {
            float2 f[8];
            float wq[8];
            #pragma unroll
            for (int q = 0; q < 8; q++) {
                int src = __shfl_sync(0xffffffffu, m.x, q0 + q);
                wq[q] = __int_as_float(__shfl_sync(0xffffffffu, m.y, q0 + q));
                f[q] = __ldg(&feat[src * 32 + lane]);
            }
            #pragma unroll
            for (int q = 0; q < 8; q++) {
                a0 += wq[q] * f[q].x;
                a1 += wq[q] * f[q].y;
            }
        }
    }
    if (pass == 0) {   // tx1 fp32 needed by pass 1 (same float2 layout)
        reinterpret_cast<float2*>(g_tx1)[warp * 32 + lane] = make_float2(a0, a1);
        // fused convert of own x row -> A cols [0,64)
        float2 xv = __ldg(&feat[warp * 32 + lane]);
        __nv_bfloat16 xh0 = __float2bfloat16_rn(xv.x);
        __nv_bfloat16 xh1 = __float2bfloat16_rn(xv.y);
        __nv_bfloat162 xhi; xhi.x = xh0; xhi.y = xh1;
        __nv_bfloat162 xlo;
        xlo.x = __float2bfloat16_rn(xv.x - __bfloat162float(xh0));
        xlo.y = __float2bfloat16_rn(xv.y - __bfloat162float(xh1));
        *reinterpret_cast<__nv_bfloat162*>(g_Ahi + warp * KTOT + 2 * lane) = xhi;
        *reinterpret_cast<__nv_bfloat162*>(g_Alo + warp * KTOT + 2 * lane) = xlo;
    }
    int cbase = pass ? 128 : 64;
    __nv_bfloat16 h0 = __float2bfloat16_rn(a0);
    __nv_bfloat16 h1 = __float2bfloat16_rn(a1);
    __nv_bfloat162 hi; hi.x = h0; hi.y = h1;
    __nv_bfloat162 lo;
    lo.x = __float2bfloat16_rn(a0 - __bfloat162float(h0));
    lo.y = __float2bfloat16_rn(a1 - __bfloat162float(h1));
    *reinterpret_cast<__nv_bfloat162*>(g_Ahi + warp * KTOT + cbase + 2 * lane) = hi;
    *reinterpret_cast<__nv_bfloat162*>(g_Alo + warp * KTOT + cbase + 2 * lane) = lo;
}

// build combined weights -> bf16 hi/lo B stored [n][k] ; biases
__global__ void weights_kernel(const float* __restrict__ Wxz,
                               const float* __restrict__ bxz,
                               const float* __restrict__ bhz,
                               const float* __restrict__ Wxh,
                               const float* __restrict__ bxh,
                               const float* __restrict__ bhh) {
    int idx = blockIdx.x * blockDim.x + threadIdx.x;
    if (idx < KTOT * NOUT) {
        int k = idx / NOUT, nn = idx % NOUT;
        int seg = k / 64, i = k % 64;
        const float* W = (nn < 64) ? Wxz : Wxh;
        int j = (nn < 64) ? nn : (nn - 64);
        float v;
        if (seg == 0)      v = W[(0 * 64 + i) * 64 + j] - W[(2 * 64 + i) * 64 + j];
        else if (seg == 1) v = W[(1 * 64 + i) * 64 + j];
        else               v = 2.0f * W[(2 * 64 + i) * 64 + j];
        __nv_bfloat16 hi = __float2bfloat16_rn(v);
        float lo = v - __bfloat162float(hi);
        g_Bhi[nn * KTOT + k] = hi;
        g_Blo[nn * KTOT + k] = __float2bfloat16_rn(lo);
    }
    if (blockIdx.x == 0 && threadIdx.x < F) {
        g_bz[threadIdx.x] = bxz[threadIdx.x] + bhz[threadIdx.x];
        g_bh[threadIdx.x] = bxh[threadIdx.x] + bhh[threadIdx.x];
    }
}

__device__ __forceinline__ float sigm(float v) { return 1.0f / (1.0f + expf(-v)); }

// ---------------- HMMA bf16x3 GEMM + fused GRU/head epilogue ----------------
// SMEM rows padded to 400B (rotates 16B per row across banks -> conflict-free LDSM)
#define SA_B 400
#define SM_AHI 0
#define SM_ALO 51200
#define SM_BHI 102400
#define SM_BLO 153600
#define GSM_TOTAL 204800
#define SC 132            // C f32 row stride

__global__ __launch_bounds__(256, 1)
void gemm_kernel(const float* __restrict__ Wlin,
                 const float* __restrict__ blin,
                 float* __restrict__ out, int n) {
    extern __shared__ char smem[];
    uint32_t sbase = smem_u32(smem);
    int tid = threadIdx.x, lane = tid & 31, wid = tid >> 5;
    int row0 = blockIdx.x * 128;

    // stage A (hi/lo) and B (hi/lo) into padded SMEM
    for (int it = tid; it < 3072; it += 256) {
        int r = it / 24, c = it % 24;
        int rg = row0 + r;
        uint4 vh = make_uint4(0, 0, 0, 0), vl = make_uint4(0, 0, 0, 0);
        if (rg < n) {
            vh = *reinterpret_cast<const uint4*>(g_Ahi + rg * KTOT + c * 8);
            vl = *reinterpret_cast<const uint4*>(g_Alo + rg * KTOT + c * 8);
        }
        *reinterpret_cast<uint4*>(smem + SM_AHI + r * SA_B + c * 16) = vh;
        *reinterpret_cast<uint4*>(smem + SM_ALO + r * SA_B + c * 16) = vl;
        uint4 bh = *reinterpret_cast<const uint4*>(g_Bhi + r * KTOT + c * 8);
        uint4 bl = *reinterpret_cast<const uint4*>(g_Blo + r * KTOT + c * 8);
        *reinterpret_cast<uint4*>(smem + SM_BHI + r * SA_B + c * 16) = bh;
        *reinterpret_cast<uint4*>(smem + SM_BLO + r * SA_B + c * 16) = bl;
    }
    __syncthreads();

    // warp tiling: 4x2 warps, each 32(M) x 64(N)
    int m0 = (wid & 3) * 32, n0 = (wid >> 2) * 64;
    int a_r = (lane & 7) + ((lane >> 3) & 1) * 8;
    int a_k = ((lane >> 4) & 1) * 8;
    int b_r = (lane & 7) + ((lane >> 4) & 1) * 8;
    int b_k = ((lane >> 3) & 1) * 8;

    float acc[2][8][4];
    #pragma unroll
    for (int i = 0; i < 2; i++)
        #pragma unroll
        for (int j = 0; j < 8; j++)
            #pragma unroll
            for (int q = 0; q < 4; q++) acc[i][j][q] = 0.0f;

    #pragma unroll
    for (int pass = 0; pass < 3; pass++) {
        uint32_t abase = sbase + ((pass == 2) ? SM_ALO : SM_AHI);
        uint32_t bbase = sbase + ((pass == 1) ? SM_BLO : SM_BHI);
        uint32_t aaddr0 = abase + (uint32_t)((m0 + a_r) * SA_B + a_k * 2);
        uint32_t aaddr1 = aaddr0 + 16 * SA_B;
        uint32_t baddr0 = bbase + (uint32_t)((n0 + b_r) * SA_B + b_k * 2);
        #pragma unroll
        for (int k = 0; k < KTOT; k += 16) {
            uint32_t a0[4], a1[4], bb[4][4];
            ldsm4(a0, aaddr0 + k * 2);
            ldsm4(a1, aaddr1 + k * 2);
            #pragma unroll
            for (int g = 0; g < 4; g++)
                ldsm4(bb[g], baddr0 + (uint32_t)(g * 16 * SA_B) + k * 2);
            #pragma unroll
            for (int g = 0; g < 4; g++) {
                mma_bf16(acc[0][2 * g],     a0, bb[g][0], bb[g][1]);
                mma_bf16(acc[0][2 * g + 1], a0, bb[g][2], bb[g][3]);
                mma_bf16(acc[1][2 * g],     a1, bb[g][0], bb[g][1]);
                mma_bf16(acc[1][2 * g + 1], a1, bb[g][2], bb[g][3]);
            }
        }
    }
    __syncthreads();

    // write C fragments to SMEM (reuses A region; 128 x 132 f32 = 67.6 KB)
    float* C = reinterpret_cast<float*>(smem);
    #pragma unroll
    for (int ms = 0; ms < 2; ms++) {
        #pragma unroll
        for (int ns = 0; ns < 8; ns++) {
            int r = m0 + ms * 16 + (lane >> 2);
            int c = n0 + ns * 8 + (lane & 3) * 2;
            float2 v0 = make_float2(acc[ms][ns][0], acc[ms][ns][1]);
            float2 v1 = make_float2(acc[ms][ns][2], acc[ms][ns][3]);
            *reinterpret_cast<float2*>(C + r * SC + c) = v0;
            *reinterpret_cast<float2*>(C + (r + 8) * SC + c) = v1;
        }
    }
    __syncthreads();

    // fused epilogue: one thread per row
    if (tid < 128) {
        int r = row0 + tid;
        const float* Cr = C + tid * SC;
        float s0 = 0.0f, s1 = 0.0f;
        #pragma unroll 4
        for (int j = 0; j < 64; j++) {
            float z = sigm(Cr[j] + __ldg(&g_bz[j]));
            float t = tanhf(Cr[j + 64] + __ldg(&g_bh[j]));
            float u = tanhf((1.0f - z) * t);
            s0 += u * __ldg(&Wlin[j * 2 + 0]);
            s1 += u * __ldg(&Wlin[j * 2 + 1]);
        }
        if (r < n) {
            out[r * 2 + 0] = sigm(s0 + __ldg(&blin[0]));
            out[r * 2 + 1] = sigm(s1 + __ldg(&blin[1]));
        }
    }
}

// ---------------- launch ----------------
extern "C" void kernel_launch(void* const* d_in, const int* in_sizes, int n_in,
                              void* d_out, int out_size) {
    const float* x    = (const float*)d_in[0];
    const int*   ei   = (const int*)d_in[1];
    const float* ew   = (const float*)d_in[2];
    const float* Wxz  = (const float*)d_in[3];
    const float* bxz  = (const float*)d_in[4];
    const float* bhz  = (const float*)d_in[6];
    const float* Wxh  = (const float*)d_in[11];
    const float* bxh  = (const float*)d_in[12];
    const float* bhh  = (const float*)d_in[14];
    const float* Wlin = (const float*)d_in[15];
    const float* blin = (const float*)d_in[16];
    float* out = (float*)d_out;

    int n = in_sizes[0] / F;       // 50000
    int E = in_sizes[2];           // 800000
    int nb = (n + SCAN_TILE - 1) / SCAN_TILE;

    cudaFuncSetAttribute(gemm_kernel, cudaFuncAttributeMaxDynamicSharedMemorySize, GSM_TOTAL);

    edge_pass1_kernel<<<(E + 255) / 256, 256>>>(ei, ew, E);
    scan_phase1_kernel<<<nb, SCAN_TILE>>>(n);
    scan_phase3_kernel<<<nb, SCAN_TILE>>>(n, nb, E);
    scatter_kernel<<<(E + 255) / 256, 256>>>(ei, ew, E);

    int prop_blocks = (n * 32 + 255) / 256;
    prop_kernel<<<prop_blocks, 256>>>(x, 0, n);
    prop_kernel<<<prop_blocks, 256>>>(x, 1, n);

    weights_kernel<<<(KTOT * NOUT + 255) / 256, 256>>>(Wxz, bxz, bhz, Wxh, bxh, bhh);
    gemm_kernel<<<(n + 127) / 128, 256, GSM_TOTAL>>>(Wlin, blin, out, n);
    (void)n_in; (void)out_size;
}